// round 12
// baseline (speedup 1.0000x reference)
#include <cuda_runtime.h>
#include <cuda_bf16.h>
#include <cstdint>

#define FULL 0xffffffffu
#define EPS 1e-8f
#define WARPS 16
#define THREADS (WARPS * 32)
#define NUM_SMS 148
#define N_MAX 100000
#define M_MAX 50000

// Quantization: x,y -> 5 bits, z -> 6 bits over [-4.75, 4.75]
#define QOFF   4.75f
#define QSC_XY (31.0f / 9.5f)
#define QSC_Z  (63.0f / 9.5f)
#define QIV_XY (9.5f / 31.0f)
#define QIV_Z  (9.5f / 63.0f)
// half-steps: hxy=0.15323, hz=0.07540 ; ||h||=0.22945 ; (1+||h||)^2=1.5116
#define FILT_THRESH 1.5120f

__device__ float4 g_points4[N_MAX];
__device__ unsigned short g_quant[N_MAX + 8];
__device__ float4 g_q4[M_MAX];

__device__ __forceinline__ float fast_sqrt(float x) {
    float r;
    asm("sqrt.approx.ftz.f32 %0, %1;" : "=f"(r) : "f"(x));
    return r;
}

__global__ void pack_kernel(const float* __restrict__ points, int N,
                            const float* __restrict__ q_coords, int M) {
    int i = blockIdx.x * blockDim.x + threadIdx.x;
    if (i < N) {
        float x = points[3 * i + 0];
        float y = points[3 * i + 1];
        float z = points[3 * i + 2];
        g_points4[i] = make_float4(x, y, z, 0.0f);
        float fx = (x + QOFF) * QSC_XY;
        float fy = (y + QOFF) * QSC_XY;
        float fz = (z + QOFF) * QSC_Z;
        unsigned short qv;
        if (fx < 0.f || fx > 31.f || fy < 0.f || fy > 31.f || fz < 0.f || fz > 63.f) {
            qv = 0xFFFFu;                     // out of range: force-pass sentinel
        } else {
            int ix = __float2int_rn(fx);
            int iy = __float2int_rn(fy);
            int iz = __float2int_rn(fz);
            qv = (unsigned short)((ix << 11) | (iy << 6) | iz);
        }
        g_quant[i] = qv;
    }
    if (i < M)
        g_q4[i] = make_float4(q_coords[3 * i + 0], q_coords[3 * i + 1],
                              q_coords[3 * i + 2], 0.0f);
}

// Conservative prefilter on SMEM-resident quantized point.
__device__ __forceinline__ bool prefilter(unsigned short qv, float4 q) {
    if (qv == 0xFFFFu) return true;
    int ux = (qv >> 11) & 31;
    int uy = (qv >> 6) & 31;
    int uz = qv & 63;
    float dx = fmaf((float)ux, QIV_XY, -QOFF) - q.x;
    float dy = fmaf((float)uy, QIV_XY, -QOFF) - q.y;
    float dz = fmaf((float)uz, QIV_Z,  -QOFF) - q.z;
    float d2q = fmaf(dx, dx, fmaf(dy, dy, dz * dz));
    return d2q <= FILT_THRESH;
}

__global__ __launch_bounds__(THREADS, 1)
void gib_kernel(const int* __restrict__ support_idxs,
                const float* __restrict__ cy_radius,
                const float* __restrict__ disk_radius,
                const float* __restrict__ disk_width,
                const float* __restrict__ cone_radius,
                const float* __restrict__ cone_inc,
                const float* __restrict__ ellip_radii,
                const float* __restrict__ lambdas,
                float* __restrict__ out,
                int N, int M, int P /* number of query pairs */)
{
    extern __shared__ unsigned short s_quant[];       // N*2 bytes (~200 KB)
    __shared__ float4 s_coef[32];
    __shared__ float  s_inc[32];
    __shared__ float  s_lamT[16][36];                 // transposed, padded, /K folded
    __shared__ float4 s_surv[WARPS][64];              // survivors (+acc alias)

    int tid = threadIdx.x;

    if (tid < 32) {
        int kind = tid >> 3;
        int g    = tid & 7;
        float a = 0.f, b = 0.f, c = 0.f, e = 0.f, inc = 0.f;
        if (kind == 0) {                 // cylinder
            float r = cy_radius[g];
            float v = -0.5f / (r * r + EPS);
            a = v; b = v;
        } else if (kind == 1) {          // cone
            float r = cone_radius[g];
            e = -0.5f / (r * r + EPS);
            inc = cone_inc[g];
        } else if (kind == 2) {          // disk
            float r = disk_radius[g];
            float w = disk_width[g];
            float v = -0.5f / (r * r + EPS);
            a = v; b = v;
            c = -0.5f / (w * w + EPS);
        } else {                         // ellipsoid
            float ex = ellip_radii[g * 3 + 0];
            float ey = ellip_radii[g * 3 + 1];
            float ez = ellip_radii[g * 3 + 2];
            a = -0.5f / (ex * ex + EPS);
            b = -0.5f / (ey * ey + EPS);
            c = -0.5f / (ez * ez + EPS);
        }
        s_coef[tid] = make_float4(a, b, c, e);
        s_inc[tid] = inc;
    }
    for (int i = tid; i < 32 * 16; i += THREADS) {
        int j = i >> 4, o = i & 15;
        s_lamT[o][j] = lambdas[i] * (1.0f / 32.0f);   // fold masked-mean 1/K
    }

    // Load quant table into SMEM (L2-resident source, coalesced uint4).
    {
        int nvec = (N + 7) / 8;                       // uint4 = 8 shorts
        const uint4* src = (const uint4*)g_quant;
        uint4* dst = (uint4*)s_quant;
        for (int i = tid; i < nvec; i += THREADS)
            dst[i] = src[i];
    }
    __syncthreads();

    int lane = tid & 31;
    int wid  = tid >> 5;
    unsigned ltmask = (1u << lane) - 1u;

    float4 cf  = s_coef[lane];
    float  inc = s_inc[lane];

    int gw     = blockIdx.x * WARPS + wid;
    int stride = gridDim.x * WARPS;

    int p = gw;
    if (p >= P) return;

    // ---- Prologue: fully stage pair p; prefetch idx for p+stride ----
    int m0 = 2 * p;
    int m1 = min(2 * p + 1, M - 1);
    int ia = __ldcg(&support_idxs[m0 * 32 + lane]);
    int ib = __ldcg(&support_idxs[m1 * 32 + lane]);
    float4 qv0 = __ldg(&g_q4[m0]);
    float4 qv1 = __ldg(&g_q4[m1]);
    bool passA = prefilter(s_quant[ia], qv0);
    bool passB = prefilter(s_quant[ib], qv1);
    float4 pa = make_float4(0.f, 0.f, 0.f, 0.f);
    float4 pb = make_float4(0.f, 0.f, 0.f, 0.f);
    if (passA) pa = __ldcg(&g_points4[ia]);
    if (passB) pb = __ldcg(&g_points4[ib]);

    int pn = p + stride;
    int ian = ia, ibn = ib;
    if (pn < P) {
        ian = __ldcg(&support_idxs[(2 * pn) * 32 + lane]);
        ibn = __ldcg(&support_idxs[min(2 * pn + 1, M - 1) * 32 + lane]);
    }

    while (p < P) {
        // ---- Stage pair pn: quant filter + conditional gather (in flight) ----
        float4 qv0n = qv0, qv1n = qv1;
        bool passAn = false, passBn = false;
        float4 pan = pa, pbn = pb;
        if (pn < P) {
            int mn0 = 2 * pn;
            int mn1 = min(2 * pn + 1, M - 1);
            qv0n = __ldg(&g_q4[mn0]);
            qv1n = __ldg(&g_q4[mn1]);
            passAn = prefilter(s_quant[ian], qv0n);
            passBn = prefilter(s_quant[ibn], qv1n);
            pan = make_float4(0.f, 0.f, 0.f, 0.f);
            pbn = make_float4(0.f, 0.f, 0.f, 0.f);
            if (passAn) pan = __ldcg(&g_points4[ian]);
            if (passBn) pbn = __ldcg(&g_points4[ibn]);
        }
        int pnn = pn + stride;
        int ian2 = ian, ibn2 = ibn;
        if (pnn < P) {
            ian2 = __ldcg(&support_idxs[(2 * pnn) * 32 + lane]);
            ibn2 = __ldcg(&support_idxs[min(2 * pnn + 1, M - 1) * 32 + lane]);
        }

        // ---- Compute current pair (pa/pb issued last iteration) ----
        float x2a = 0.f, y2a = 0.f, za = 0.f, rxya = 0.f, d2a = 9e9f;
        float x2b = 0.f, y2b = 0.f, zb = 0.f, rxyb = 0.f, d2b = 9e9f;
        if (passA) {
            float xa = pa.x - qv0.x, ya = pa.y - qv0.y;
            za = pa.z - qv0.z;
            x2a = xa * xa; y2a = ya * ya;
            float xy2a = x2a + y2a;
            d2a = xy2a + za * za;
            rxya = fast_sqrt(xy2a + EPS);
        }
        if (passB) {
            float xb = pb.x - qv1.x, yb = pb.y - qv1.y;
            zb = pb.z - qv1.z;
            x2b = xb * xb; y2b = yb * yb;
            float xy2b = x2b + y2b;
            d2b = xy2b + zb * zb;
            rxyb = fast_sqrt(xy2b + EPS);
        }

        bool alive0 = (d2a <= 1.0f);
        bool alive1 = (d2b <= 1.0f) && (m1 == 2 * p + 1);
        unsigned b0 = __ballot_sync(FULL, alive0);
        unsigned b1 = __ballot_sync(FULL, alive1);
        int n0 = __popc(b0);
        int n1 = __popc(b1);

        float4* surv = &s_surv[wid][0];     // slots [0..31]=q0, [32..63]=q1
        if (alive0) surv[__popc(b0 & ltmask)]      = make_float4(x2a, y2a, za, rxya);
        if (alive1) surv[32 + __popc(b1 & ltmask)] = make_float4(x2b, y2b, zb, rxyb);
        __syncwarp();

        float acc0 = 0.0f, acc1 = 0.0f;
        int nmax = max(n0, n1);
        #pragma unroll 2
        for (int j = 0; j < nmax; j++) {
            if (j < n0) {
                float4 v = surv[j];
                float dd = fmaf(-inc, v.z, v.w);
                float t = fmaf(cf.x, v.x,
                          fmaf(cf.y, v.y,
                          fmaf(cf.z, v.z * v.z, (cf.w * dd) * dd)));
                acc0 += __expf(t);
            }
            if (j < n1) {
                float4 v = surv[32 + j];
                float dd = fmaf(-inc, v.z, v.w);
                float t = fmaf(cf.x, v.x,
                          fmaf(cf.y, v.y,
                          fmaf(cf.z, v.z * v.z, (cf.w * dd) * dd)));
                acc1 += __expf(t);
            }
        }
        __syncwarp();

        // Stage accumulators (alias survivor region — survivor data now dead).
        float* accp = (float*)surv;
        accp[lane]      = acc0;
        accp[32 + lane] = acc1;
        __syncwarp();

        // Epilogue: lanes 0-15 -> q0, lanes 16-31 -> q1; two partial chains.
        int qsel = lane >> 4;
        int o    = lane & 15;
        int mst  = qsel ? (2 * p + 1) : m0;
        if (mst < M) {
            const float* arow = accp + qsel * 32;
            float ot0 = 0.0f, ot1 = 0.0f;
            #pragma unroll
            for (int j = 0; j < 16; j += 4) {
                float4 lamA = *(const float4*)&s_lamT[o][j];
                float4 aA   = *(const float4*)&arow[j];
                ot0 = fmaf(aA.x, lamA.x,
                      fmaf(aA.y, lamA.y,
                      fmaf(aA.z, lamA.z,
                      fmaf(aA.w, lamA.w, ot0))));
                float4 lamB = *(const float4*)&s_lamT[o][j + 16];
                float4 aB   = *(const float4*)&arow[j + 16];
                ot1 = fmaf(aB.x, lamB.x,
                      fmaf(aB.y, lamB.y,
                      fmaf(aB.z, lamB.z,
                      fmaf(aB.w, lamB.w, ot1))));
            }
            out[mst * 16 + o] = ot0 + ot1;
        }
        __syncwarp();

        // ---- Rotate pipeline ----
        p = pn; pn = pnn;
        m0 = 2 * p;
        m1 = min(2 * p + 1, M - 1);
        ia = ian; ib = ibn;
        ian = ian2; ibn = ibn2;
        qv0 = qv0n; qv1 = qv1n;
        passA = passAn; passB = passBn;
        pa = pan; pb = pbn;
    }
}

extern "C" void kernel_launch(void* const* d_in, const int* in_sizes, int n_in,
                              void* d_out, int out_size) {
    const float* points       = (const float*)d_in[0];
    const float* q_coords     = (const float*)d_in[1];
    const int*   support_idxs = (const int*)  d_in[2];
    const float* cy_radius    = (const float*)d_in[3];
    const float* disk_radius  = (const float*)d_in[4];
    const float* disk_width   = (const float*)d_in[5];
    const float* cone_radius  = (const float*)d_in[6];
    const float* cone_inc     = (const float*)d_in[7];
    const float* ellip_radii  = (const float*)d_in[8];
    const float* lambdas      = (const float*)d_in[9];
    float* out = (float*)d_out;

    int N = in_sizes[0] / 3;   // points has N*3 elements
    int M = in_sizes[1] / 3;   // q_coords has M*3 elements
    int P = (M + 1) / 2;       // query pairs

    int packN = N > M ? N : M;
    pack_kernel<<<(packN + 255) / 256, 256>>>(points, N, q_coords, M);

    // Dynamic smem for the quant table (rounded to uint4 granularity).
    int smemBytes = ((N + 7) / 8) * 16;
    cudaFuncSetAttribute(gib_kernel,
                         cudaFuncAttributeMaxDynamicSharedMemorySize, smemBytes);

    int needBlocks = (P + WARPS - 1) / WARPS;
    int blocks = needBlocks < NUM_SMS ? needBlocks : NUM_SMS;
    gib_kernel<<<blocks, THREADS, smemBytes>>>(support_idxs,
                                    cy_radius, disk_radius, disk_width,
                                    cone_radius, cone_inc, ellip_radii,
                                    lambdas, out, N, M, P);
}

// round 13
// speedup vs baseline: 1.2254x; 1.2254x over previous
#include <cuda_runtime.h>
#include <cuda_bf16.h>
#include <cstdint>

#define FULL 0xffffffffu
#define EPS 1e-8f
#define WARPS 32
#define THREADS (WARPS * 32)
#define NUM_SMS 148
#define N_MAX 100000
#define M_MAX 50000

// Quantization: x,y -> 5 bits, z -> 6 bits over [-4.75, 4.75]
#define QOFF   4.75f
#define QSC_XY (31.0f / 9.5f)
#define QSC_Z  (63.0f / 9.5f)
#define QIV_XY (9.5f / 31.0f)
#define QIV_Z  (9.5f / 63.0f)
// half-steps: hxy=0.15323, hz=0.07540 ; ||h||=0.22945 ; (1+||h||)^2=1.5116
#define FILT_THRESH 1.5120f

__device__ float4 g_points4[N_MAX];
__device__ unsigned short g_quant[N_MAX + 8];
__device__ float4 g_q4[M_MAX];

__device__ __forceinline__ float fast_sqrt(float x) {
    float r;
    asm("sqrt.approx.ftz.f32 %0, %1;" : "=f"(r) : "f"(x));
    return r;
}

__global__ void pack_kernel(const float* __restrict__ points, int N,
                            const float* __restrict__ q_coords, int M) {
    int i = blockIdx.x * blockDim.x + threadIdx.x;
    if (i < N) {
        float x = points[3 * i + 0];
        float y = points[3 * i + 1];
        float z = points[3 * i + 2];
        g_points4[i] = make_float4(x, y, z, 0.0f);
        float fx = (x + QOFF) * QSC_XY;
        float fy = (y + QOFF) * QSC_XY;
        float fz = (z + QOFF) * QSC_Z;
        unsigned short qv;
        if (fx < 0.f || fx > 31.f || fy < 0.f || fy > 31.f || fz < 0.f || fz > 63.f) {
            qv = 0xFFFFu;                     // out of range: force-pass sentinel
        } else {
            int ix = __float2int_rn(fx);
            int iy = __float2int_rn(fy);
            int iz = __float2int_rn(fz);
            qv = (unsigned short)((ix << 11) | (iy << 6) | iz);
        }
        g_quant[i] = qv;
    }
    if (i < M)
        g_q4[i] = make_float4(q_coords[3 * i + 0], q_coords[3 * i + 1],
                              q_coords[3 * i + 2], 0.0f);
}

// Conservative prefilter on SMEM-resident quantized point (no false negatives).
__device__ __forceinline__ bool prefilter(unsigned short qv, float4 q) {
    if (qv == 0xFFFFu) return true;
    int ux = (qv >> 11) & 31;
    int uy = (qv >> 6) & 31;
    int uz = qv & 63;
    float dx = fmaf((float)ux, QIV_XY, -QOFF) - q.x;
    float dy = fmaf((float)uy, QIV_XY, -QOFF) - q.y;
    float dz = fmaf((float)uz, QIV_Z,  -QOFF) - q.z;
    float d2q = fmaf(dx, dx, fmaf(dy, dy, dz * dz));
    return d2q <= FILT_THRESH;
}

__global__ __launch_bounds__(THREADS, 1)
void gib_kernel(const int* __restrict__ support_idxs,
                const float* __restrict__ cy_radius,
                const float* __restrict__ disk_radius,
                const float* __restrict__ disk_width,
                const float* __restrict__ cone_radius,
                const float* __restrict__ cone_inc,
                const float* __restrict__ ellip_radii,
                const float* __restrict__ lambdas,
                float* __restrict__ out,
                int N, int M)
{
    extern __shared__ unsigned short s_quant[];       // N*2 bytes (~195 KB)
    __shared__ float4 s_coef[32];
    __shared__ float  s_inc[32];
    __shared__ float  s_lamT[16][36];                 // transposed, padded, /K folded
    __shared__ float4 s_surv[WARPS][32];              // survivors (+acc alias)

    int tid = threadIdx.x;

    if (tid < 32) {
        int kind = tid >> 3;
        int g    = tid & 7;
        float a = 0.f, b = 0.f, c = 0.f, e = 0.f, inc = 0.f;
        if (kind == 0) {                 // cylinder
            float r = cy_radius[g];
            float v = -0.5f / (r * r + EPS);
            a = v; b = v;
        } else if (kind == 1) {          // cone
            float r = cone_radius[g];
            e = -0.5f / (r * r + EPS);
            inc = cone_inc[g];
        } else if (kind == 2) {          // disk
            float r = disk_radius[g];
            float w = disk_width[g];
            float v = -0.5f / (r * r + EPS);
            a = v; b = v;
            c = -0.5f / (w * w + EPS);
        } else {                         // ellipsoid
            float ex = ellip_radii[g * 3 + 0];
            float ey = ellip_radii[g * 3 + 1];
            float ez = ellip_radii[g * 3 + 2];
            a = -0.5f / (ex * ex + EPS);
            b = -0.5f / (ey * ey + EPS);
            c = -0.5f / (ez * ez + EPS);
        }
        s_coef[tid] = make_float4(a, b, c, e);
        s_inc[tid] = inc;
    }
    for (int i = tid; i < 32 * 16; i += THREADS) {
        int j = i >> 4, o = i & 15;
        s_lamT[o][j] = lambdas[i] * (1.0f / 32.0f);   // fold masked-mean 1/K
    }

    // Load quant table into SMEM (coalesced uint4 stream from L2).
    {
        int nvec = (N + 7) / 8;                       // uint4 = 8 shorts
        const uint4* src = (const uint4*)g_quant;
        uint4* dst = (uint4*)s_quant;
        for (int i = tid; i < nvec; i += THREADS)
            dst[i] = src[i];
    }
    __syncthreads();

    int lane = tid & 31;
    int wid  = tid >> 5;
    unsigned ltmask = (1u << lane) - 1u;

    float4 cf  = s_coef[lane];
    float  inc = s_inc[lane];

    int gw     = blockIdx.x * WARPS + wid;
    int stride = gridDim.x * WARPS;

    int q = gw;
    if (q >= M) return;

    // idx prefetch pipeline (1 deep; cheap register state)
    int idn = __ldcg(&support_idxs[q * 32 + lane]);

    for (; q < M; q += stride) {
        int id = idn;
        int qn = q + stride;
        if (qn < M)
            idn = __ldcg(&support_idxs[qn * 32 + lane]);

        float4 qc = __ldg(&g_q4[q]);                  // broadcast, L1-resident

        // Stage 1: SMEM prefilter (~14% pass, zero L1tex gather cost)
        bool pass = prefilter(s_quant[id], qc);

        // Stage 2: exact fetch + test only for passing lanes
        float x2 = 0.f, y2 = 0.f, zz = 0.f, rxy = 0.f, d2 = 9e9f;
        if (pass) {
            float4 pt = __ldcg(&g_points4[id]);
            float x = pt.x - qc.x, y = pt.y - qc.y;
            zz = pt.z - qc.z;
            x2 = x * x; y2 = y * y;
            float xy2 = x2 + y2;
            d2 = xy2 + zz * zz;
            rxy = fast_sqrt(xy2 + EPS);
        }

        bool alive = (d2 <= 1.0f);
        unsigned bal = __ballot_sync(FULL, alive);
        int n = __popc(bal);

        float4* surv = &s_surv[wid][0];
        if (alive) surv[__popc(bal & ltmask)] = make_float4(x2, y2, zz, rxy);
        __syncwarp();

        float acc = 0.0f;
        for (int j = 0; j < n; j++) {
            float4 v = surv[j];
            float dd = fmaf(-inc, v.z, v.w);
            float t = fmaf(cf.x, v.x,
                      fmaf(cf.y, v.y,
                      fmaf(cf.z, v.z * v.z, (cf.w * dd) * dd)));
            acc += __expf(t);
        }
        __syncwarp();

        // Stage accumulators (alias survivor region — survivor data is dead).
        float* accp = (float*)surv;
        accp[lane] = acc;
        __syncwarp();

        // Epilogue: full warp. Lane l: output o=l&15, j-range half = l>>4.
        int half = lane >> 4;
        int o    = lane & 15;
        const float* arow = accp + half * 16;
        const float* lamo = &s_lamT[o][half * 16];
        float ot = 0.0f;
        #pragma unroll
        for (int j = 0; j < 16; j += 4) {
            float4 lam4 = *(const float4*)&lamo[j];
            float4 a4   = *(const float4*)&arow[j];
            ot = fmaf(a4.x, lam4.x,
                 fmaf(a4.y, lam4.y,
                 fmaf(a4.z, lam4.z,
                 fmaf(a4.w, lam4.w, ot))));
        }
        ot += __shfl_xor_sync(FULL, ot, 16);
        if (lane < 16)
            out[q * 16 + o] = ot;
        __syncwarp();
    }
}

extern "C" void kernel_launch(void* const* d_in, const int* in_sizes, int n_in,
                              void* d_out, int out_size) {
    const float* points       = (const float*)d_in[0];
    const float* q_coords     = (const float*)d_in[1];
    const int*   support_idxs = (const int*)  d_in[2];
    const float* cy_radius    = (const float*)d_in[3];
    const float* disk_radius  = (const float*)d_in[4];
    const float* disk_width   = (const float*)d_in[5];
    const float* cone_radius  = (const float*)d_in[6];
    const float* cone_inc     = (const float*)d_in[7];
    const float* ellip_radii  = (const float*)d_in[8];
    const float* lambdas      = (const float*)d_in[9];
    float* out = (float*)d_out;

    int N = in_sizes[0] / 3;   // points has N*3 elements
    int M = in_sizes[1] / 3;   // q_coords has M*3 elements

    int packN = N > M ? N : M;
    pack_kernel<<<(packN + 255) / 256, 256>>>(points, N, q_coords, M);

    // Dynamic smem for the quant table (rounded to uint4 granularity).
    int smemBytes = ((N + 7) / 8) * 16;
    cudaFuncSetAttribute(gib_kernel,
                         cudaFuncAttributeMaxDynamicSharedMemorySize, smemBytes);

    int needBlocks = (M + WARPS - 1) / WARPS;
    int blocks = needBlocks < NUM_SMS ? needBlocks : NUM_SMS;
    gib_kernel<<<blocks, THREADS, smemBytes>>>(support_idxs,
                                    cy_radius, disk_radius, disk_width,
                                    cone_radius, cone_inc, ellip_radii,
                                    lambdas, out, N, M);
}